// round 7
// baseline (speedup 1.0000x reference)
#include <cuda_runtime.h>
#include <stdint.h>

// LSTM: H=50, input 1, T=1024, B independent batch elements.
// One block (224 threads, 7 warps) per batch element; ONE barrier per step.
// Row permutation puts all 4 gates of hidden j in one warp:
//   warp w, lane = g*8 + k  owns gate row  g*50 + (8w + k),  g in {i,f,g,o}.
// Each thread: full row dot-product (13 broadcast LDS.128 + 26 FFMA2,
// 4 accumulator chains), activation, then 3 shfl.down (8,16,24) deliver
// f,g,o to the i-lane (g==0), which holds c privately and writes h to the
// double-buffered h_sh. No shared gate traffic, no second __syncthreads.
// Gate order (PyTorch): i[0:50], f[50:100], g[100:150], o[150:200].

#define HH 50
#define TT 1024
#define BT 224

typedef unsigned long long ull;

__device__ __forceinline__ float sigf(float x) {
    return 1.0f / (1.0f + __expf(-x));
}
__device__ __forceinline__ float tanhfast(float x) {
    return fmaf(2.0f, sigf(2.0f * x), -1.0f);   // tanh via 2*sig(2x)-1
}
__device__ __forceinline__ void fma2(ull& d, ull a, ull b) {
    asm("fma.rn.f32x2 %0, %1, %2, %0;" : "+l"(d) : "l"(a), "l"(b));
}
__device__ __forceinline__ ull pack2(float lo, float hi) {
    return ((ull)__float_as_uint(hi) << 32) | (ull)__float_as_uint(lo);
}
__device__ __forceinline__ float sum2(ull a) {
    return __uint_as_float((unsigned)a) + __uint_as_float((unsigned)(a >> 32));
}

__global__ void __launch_bounds__(BT, 4)
lstm_kernel(const float* __restrict__ x,      // [B, T, 1]
            const float* __restrict__ W_ih,   // [200, 1]
            const float* __restrict__ W_hh,   // [200, 50]
            const float* __restrict__ b_ih,   // [200]
            const float* __restrict__ b_hh,   // [200]
            const float* __restrict__ W_lin,  // [1, 50]
            const float* __restrict__ b_lin,  // [1]
            float* __restrict__ out)          // [B, 1]
{
    __shared__ __align__(16) float h_sh[2][56];  // double-buffered; pad 50..55
    __shared__ float x_sh[TT];

    const int tid  = threadIdx.x;
    const int lane = tid & 31;
    const int g    = lane >> 3;            // gate index: 0=i 1=f 2=g 3=o
    const int jj   = (tid >> 5) * 8 + (lane & 7);   // hidden index 0..55
    const bool active = (jj < HH);
    const int  b   = blockIdx.x;

    for (int i = tid; i < TT; i += BT) x_sh[i] = x[(size_t)b * TT + i];
    if (tid < 2 * 56) ((float*)h_sh)[tid] = 0.0f;   // h0 = 0; pads stay 0

    // This thread's gate row: g*50 + jj (zeroed if inactive).
    ull wp[26];
    float wih = 0.0f, bias = 0.0f;
    {
        const int row = g * HH + jj;
        if (active) { wih = W_ih[row]; bias = b_ih[row] + b_hh[row]; }
        #pragma unroll
        for (int q = 0; q < 26; q++) {
            float lo = (active && 2 * q     < HH) ? W_hh[row * HH + 2 * q]     : 0.0f;
            float hi = (active && 2 * q + 1 < HH) ? W_hh[row * HH + 2 * q + 1] : 0.0f;
            wp[q] = pack2(lo, hi);
        }
    }
    // Activation params: g==2 -> tanh(x) = 2*sig(2x)-1, else sigmoid.
    const float am = (g == 2) ? 2.0f : 1.0f;
    const float ad = (g == 2) ? -1.0f : 0.0f;
    const bool  owner = (g == 0) && active;   // i-lane updates c, h
    float c = 0.0f;
    __syncthreads();

    #pragma unroll 1
    for (int t = 0; t < TT; t++) {
        const int rb = t & 1;
        const ulonglong2* h2 = (const ulonglong2*)h_sh[rb];
        ull a0 = (ull)__float_as_uint(fmaf(x_sh[t], wih, bias));
        ull a1 = 0ull, a2 = 0ull, a3 = 0ull;     // 4 chains (depth <= 7)
        #pragma unroll
        for (int q = 0; q < 13; q += 2) {
            ulonglong2 hv = h2[q];               // broadcast LDS.128
            fma2(a0, wp[2 * q],     hv.x);
            fma2(a1, wp[2 * q + 1], hv.y);
        }
        #pragma unroll
        for (int q = 1; q < 13; q += 2) {
            ulonglong2 hv = h2[q];
            fma2(a2, wp[2 * q],     hv.x);
            fma2(a3, wp[2 * q + 1], hv.y);
        }
        const float s = (sum2(a0) + sum2(a1)) + (sum2(a2) + sum2(a3));
        const float v = fmaf(am, sigf(am * s), ad);   // activated gate
        // Route f,g,o to the i-lane (lanes with g==0).
        const float vf = __shfl_down_sync(0xFFFFFFFFu, v, 8);
        const float vg = __shfl_down_sync(0xFFFFFFFFu, v, 16);
        const float vo = __shfl_down_sync(0xFFFFFFFFu, v, 24);
        if (owner) {
            c = fmaf(vf, c, v * vg);             // sig(f)*c + sig(i)*tanh(g)
            h_sh[rb ^ 1][jj] = vo * tanhfast(c); // sig(o)*tanh(c)
        }
        __syncthreads();
    }

    // Final h in buffer (1023&1)^1 == 0. Linear head.
    if (tid == 0) {
        float s = b_lin[0];
        #pragma unroll 1
        for (int q = 0; q < HH; q++) s = fmaf(h_sh[0][q], W_lin[q], s);
        out[b] = s;
    }
}

extern "C" void kernel_launch(void* const* d_in, const int* in_sizes, int n_in,
                              void* d_out, int out_size) {
    const float* x     = (const float*)d_in[0];
    const float* W_ih  = (const float*)d_in[1];
    const float* W_hh  = (const float*)d_in[2];
    const float* b_ih  = (const float*)d_in[3];
    const float* b_hh  = (const float*)d_in[4];
    const float* W_lin = (const float*)d_in[5];
    const float* b_lin = (const float*)d_in[6];
    float* out = (float*)d_out;

    int B = in_sizes[0] / TT;
    lstm_kernel<<<B, BT>>>(x, W_ih, W_hh, b_ih, b_hh, W_lin, b_lin, out);
}

// round 8
// speedup vs baseline: 1.2623x; 1.2623x over previous
#include <cuda_runtime.h>
#include <stdint.h>

// LSTM: H=50, input 1, T=1024, B independent batch elements.
// R1's proven layout (1 gate row per thread, smem act exchange, 2 barriers)
// but each block processes TWO batch elements sharing the weight registers.
// Thread j (<200) owns gate row j: 26 packed f32x2 weight regs, and runs
// 4 independent accumulator chains (2 per batch element).
// Phase 2 uses 100 threads (2 batches x 50 hidden), c private per thread.
// Gate order (PyTorch): i[0:50], f[50:100], g[100:150], o[150:200].

#define HH 50
#define GG 200
#define TT 1024
#define BT 224

typedef unsigned long long ull;

__device__ __forceinline__ float sigf(float x) {
    return 1.0f / (1.0f + __expf(-x));
}
__device__ __forceinline__ float tanhfast(float x) {
    return fmaf(2.0f, sigf(2.0f * x), -1.0f);   // tanh via 2*sig(2x)-1
}
__device__ __forceinline__ void fma2(ull& d, ull a, ull b) {
    asm("fma.rn.f32x2 %0, %1, %2, %0;" : "+l"(d) : "l"(a), "l"(b));
}
__device__ __forceinline__ ull pack2(float lo, float hi) {
    return ((ull)__float_as_uint(hi) << 32) | (ull)__float_as_uint(lo);
}
__device__ __forceinline__ float sum2(ull a) {
    return __uint_as_float((unsigned)a) + __uint_as_float((unsigned)(a >> 32));
}

__global__ void __launch_bounds__(BT, 3)
lstm_kernel(const float* __restrict__ x,      // [B, T, 1]
            const float* __restrict__ W_ih,   // [200, 1]
            const float* __restrict__ W_hh,   // [200, 50]
            const float* __restrict__ b_ih,   // [200]
            const float* __restrict__ b_hh,   // [200]
            const float* __restrict__ W_lin,  // [1, 50]
            const float* __restrict__ b_lin,  // [1]
            float* __restrict__ out,          // [B, 1]
            int B)
{
    __shared__ __align__(16) float h_sh[2][56];   // per-batch h; pads stay 0
    __shared__ float act_sh[2][GG];
    __shared__ float x_sh[2][TT];

    const int j  = threadIdx.x;
    const int b0 = blockIdx.x * 2;

    // Stage the two x rows (zero-fill past B).
    for (int i = j; i < 2 * TT; i += BT) {
        const int m = i >> 10, t = i & (TT - 1);
        x_sh[m][t] = (b0 + m < B) ? x[(size_t)(b0 + m) * TT + t] : 0.0f;
    }
    if (j < 112) ((float*)h_sh)[j] = 0.0f;        // h0 = 0

    float wih = 0.0f, bias = 0.0f;
    ull wp[26];
    if (j < GG) {
        wih  = W_ih[j];
        bias = b_ih[j] + b_hh[j];
        #pragma unroll
        for (int q = 0; q < 26; q++) {
            float lo = (2 * q     < HH) ? W_hh[j * HH + 2 * q]     : 0.0f;
            float hi = (2 * q + 1 < HH) ? W_hh[j * HH + 2 * q + 1] : 0.0f;
            wp[q] = pack2(lo, hi);
        }
    }
    const bool gate_g = (j >= 100 && j < 150);
    // Phase-2 mapping: threads 0..99 -> (batch mu, hidden ku).
    const int mu = (j >= HH) ? 1 : 0;
    const int ku = j - mu * HH;
    float c = 0.0f;

    __syncthreads();

    #pragma unroll 1
    for (int t = 0; t < TT; t++) {
        if (j < GG) {
            ull a00 = (ull)__float_as_uint(fmaf(x_sh[0][t], wih, bias));
            ull a10 = (ull)__float_as_uint(fmaf(x_sh[1][t], wih, bias));
            ull a01 = 0ull, a11 = 0ull;
            const ulonglong2* h20 = (const ulonglong2*)h_sh[0];
            const ulonglong2* h21 = (const ulonglong2*)h_sh[1];
            #pragma unroll
            for (int q = 0; q < 13; q++) {
                ulonglong2 hv0 = h20[q];          // broadcast LDS.128
                fma2(a00, wp[2 * q],     hv0.x);
                fma2(a01, wp[2 * q + 1], hv0.y);
                ulonglong2 hv1 = h21[q];
                fma2(a10, wp[2 * q],     hv1.x);
                fma2(a11, wp[2 * q + 1], hv1.y);
            }
            const float s0 = sum2(a00) + sum2(a01);
            const float s1 = sum2(a10) + sum2(a11);
            act_sh[0][j] = gate_g ? tanhfast(s0) : sigf(s0);
            act_sh[1][j] = gate_g ? tanhfast(s1) : sigf(s1);
        }
        __syncthreads();
        if (j < 2 * HH) {
            const float gi = act_sh[mu][ku];
            const float gf = act_sh[mu][ku +  50];
            const float gg = act_sh[mu][ku + 100];
            const float go = act_sh[mu][ku + 150];
            c = fmaf(gf, c, gi * gg);
            h_sh[mu][ku] = go * tanhfast(c);
        }
        __syncthreads();
    }

    // Linear head: one thread per batch element.
    if (j < 2 && b0 + j < B) {
        float s = b_lin[0];
        #pragma unroll 1
        for (int k = 0; k < HH; k++) s = fmaf(h_sh[j][k], W_lin[k], s);
        out[b0 + j] = s;
    }
}

extern "C" void kernel_launch(void* const* d_in, const int* in_sizes, int n_in,
                              void* d_out, int out_size) {
    const float* x     = (const float*)d_in[0];
    const float* W_ih  = (const float*)d_in[1];
    const float* W_hh  = (const float*)d_in[2];
    const float* b_ih  = (const float*)d_in[3];
    const float* b_hh  = (const float*)d_in[4];
    const float* W_lin = (const float*)d_in[5];
    const float* b_lin = (const float*)d_in[6];
    float* out = (float*)d_out;

    int B = in_sizes[0] / TT;
    int grid = (B + 1) / 2;
    lstm_kernel<<<grid, BT>>>(x, W_ih, W_hh, b_ih, b_hh, W_lin, b_lin, out, B);
}

// round 9
// speedup vs baseline: 2.6401x; 2.0916x over previous
#include <cuda_runtime.h>
#include <stdint.h>

// LSTM: H=50, input 1, T=1024, B independent batch elements.
// R=2 row-blocking (best measured FFMA2:LDS ratio, 1:4) with M=2 batches
// per block sharing the weight registers.
//   thread j<50  : rows j     (i-gate), j+100 (g-gate), both batches
//   thread 50..99: rows j     (f-gate), j+100 (o-gate), both batches
// Per thread per step: 26 broadcast LDS.128 + 104 fma.rn.f32x2 (8 chains).
// Exchange: thread k<50 writes p[m][k] = sig(i)*tanh(g); thread k+50 holds
// f,o and private c[m]: c = sig(f)*c + p; h = sig(o)*tanh(c).
// Activations via hardware tanh.approx.f32 (sigmoid = 0.5*tanh(x/2)+0.5).
// Two __syncthreads per step, single h buffer.
// Gate order (PyTorch): i[0:50], f[50:100], g[100:150], o[150:200].

#define HH 50
#define TT 1024
#define BT 128

typedef unsigned long long ull;

__device__ __forceinline__ float tanha(float x) {
    float y;
    asm("tanh.approx.f32 %0, %1;" : "=f"(y) : "f"(x));
    return y;
}
__device__ __forceinline__ float sigt(float x) {
    return fmaf(0.5f, tanha(0.5f * x), 0.5f);
}
__device__ __forceinline__ void fma2(ull& d, ull a, ull b) {
    asm("fma.rn.f32x2 %0, %1, %2, %0;" : "+l"(d) : "l"(a), "l"(b));
}
__device__ __forceinline__ ull pack2(float lo, float hi) {
    return ((ull)__float_as_uint(hi) << 32) | (ull)__float_as_uint(lo);
}
__device__ __forceinline__ float sum2(ull a) {
    return __uint_as_float((unsigned)a) + __uint_as_float((unsigned)(a >> 32));
}

__global__ void __launch_bounds__(BT, 3)
lstm_kernel(const float* __restrict__ x,      // [B, T, 1]
            const float* __restrict__ W_ih,   // [200, 1]
            const float* __restrict__ W_hh,   // [200, 50]
            const float* __restrict__ b_ih,   // [200]
            const float* __restrict__ b_hh,   // [200]
            const float* __restrict__ W_lin,  // [1, 50]
            const float* __restrict__ b_lin,  // [1]
            float* __restrict__ out,          // [B, 1]
            int B)
{
    __shared__ __align__(16) float h_sh[2][56];  // per-batch h; pads 50..55 = 0
    __shared__ float p_sh[2][HH];                // sig(i)*tanh(g) handoff
    __shared__ float x_sh[2][TT];

    const int j  = threadIdx.x;
    const int b0 = blockIdx.x * 2;

    for (int i = j; i < 2 * TT; i += BT) {
        const int m = i >> 10, t = i & (TT - 1);
        x_sh[m][t] = (b0 + m < B) ? x[(size_t)(b0 + m) * TT + t] : 0.0f;
    }
    if (j < 112) ((float*)h_sh)[j] = 0.0f;       // h0 = 0; pads stay 0

    // Two gate rows per thread: rA = j, rB = j + 100 (shared across batches).
    ull wpA[13], wpB[13];
    float wihA = 0.0f, wihB = 0.0f, biasA = 0.0f, biasB = 0.0f;
    const bool p1  = (j < 100);
    const bool low = (j < 50);                   // i/g thread
    if (p1) {
        const int rA = j, rB = j + 100;
        wihA  = W_ih[rA];            wihB  = W_ih[rB];
        biasA = b_ih[rA] + b_hh[rA]; biasB = b_ih[rB] + b_hh[rB];
        #pragma unroll
        for (int q = 0; q < 13; q++) {
            float a0 = (4 * q     < HH) ? W_hh[rA * HH + 4 * q]     : 0.0f;
            float a1 = (4 * q + 1 < HH) ? W_hh[rA * HH + 4 * q + 1] : 0.0f;
            float a2 = (4 * q + 2 < HH) ? W_hh[rA * HH + 4 * q + 2] : 0.0f;
            float a3 = (4 * q + 3 < HH) ? W_hh[rA * HH + 4 * q + 3] : 0.0f;
            // pack row A as two ulls per LDS.128 quad -> store interleaved:
            wpA[q] = pack2(a0, a1);
            // reuse: second half packed below in wpB-style array? No:
            // keep 13 quads: (a0,a1) in wpA[q], (a2,a3) folded via wpB? no.
            (void)a2; (void)a3;
        }
        // Repack properly: 13 LDS.128 -> 26 ull halves per row. To keep 13+13
        // arrays, fold halves: wpA2/wpB2 below.
    }
    // Full packing: 26 ulls per row is too many arrays; use 2D arrays.
    ull wA[26], wB[26];
    if (p1) {
        const int rA = j, rB = j + 100;
        #pragma unroll
        for (int q = 0; q < 26; q++) {
            float l0 = (2 * q     < HH) ? W_hh[rA * HH + 2 * q]     : 0.0f;
            float l1 = (2 * q + 1 < HH) ? W_hh[rA * HH + 2 * q + 1] : 0.0f;
            float m0 = (2 * q     < HH) ? W_hh[rB * HH + 2 * q]     : 0.0f;
            float m1 = (2 * q + 1 < HH) ? W_hh[rB * HH + 2 * q + 1] : 0.0f;
            wA[q] = pack2(l0, l1);
            wB[q] = pack2(m0, m1);
        }
    }
    float c0 = 0.0f, c1 = 0.0f;                  // owned by threads 50..99
    __syncthreads();

    #pragma unroll 1
    for (int t = 0; t < TT; t++) {
        float a0_0 = 0.f, a1_0 = 0.f, a0_1 = 0.f, a1_1 = 0.f;
        if (p1) {
            const float xt0 = x_sh[0][t];
            const float xt1 = x_sh[1][t];
            ull aA0 = (ull)__float_as_uint(fmaf(xt0, wihA, biasA)), aA0b = 0ull;
            ull aB0 = (ull)__float_as_uint(fmaf(xt0, wihB, biasB)), aB0b = 0ull;
            ull aA1 = (ull)__float_as_uint(fmaf(xt1, wihA, biasA)), aA1b = 0ull;
            ull aB1 = (ull)__float_as_uint(fmaf(xt1, wihB, biasB)), aB1b = 0ull;
            const ulonglong2* h20 = (const ulonglong2*)h_sh[0];
            const ulonglong2* h21 = (const ulonglong2*)h_sh[1];
            #pragma unroll
            for (int q = 0; q < 13; q++) {
                ulonglong2 hv0 = h20[q];         // broadcast LDS.128, batch 0
                fma2(aA0,  wA[2 * q],     hv0.x);
                fma2(aA0b, wA[2 * q + 1], hv0.y);
                fma2(aB0,  wB[2 * q],     hv0.x);
                fma2(aB0b, wB[2 * q + 1], hv0.y);
                ulonglong2 hv1 = h21[q];         // broadcast LDS.128, batch 1
                fma2(aA1,  wA[2 * q],     hv1.x);
                fma2(aA1b, wA[2 * q + 1], hv1.y);
                fma2(aB1,  wB[2 * q],     hv1.x);
                fma2(aB1b, wB[2 * q + 1], hv1.y);
            }
            const float sA0 = sum2(aA0) + sum2(aA0b);   // i or f, batch 0
            const float sB0 = sum2(aB0) + sum2(aB0b);   // g or o, batch 0
            const float sA1 = sum2(aA1) + sum2(aA1b);   // i or f, batch 1
            const float sB1 = sum2(aB1) + sum2(aB1b);   // g or o, batch 1
            a0_0 = sigt(sA0);
            a0_1 = sigt(sA1);
            a1_0 = low ? tanha(sB0) : sigt(sB0);
            a1_1 = low ? tanha(sB1) : sigt(sB1);
            if (low) {                            // sig(i)*tanh(g)
                p_sh[0][j] = a0_0 * a1_0;
                p_sh[1][j] = a0_1 * a1_1;
            }
        }
        __syncthreads();
        if (p1 && !low) {
            const int k = j - 50;
            c0 = fmaf(a0_0, c0, p_sh[0][k]);      // sig(f)*c + i*g
            c1 = fmaf(a0_1, c1, p_sh[1][k]);
            h_sh[0][k] = a1_0 * tanha(c0);        // sig(o)*tanh(c)
            h_sh[1][k] = a1_1 * tanha(c1);
        }
        __syncthreads();
    }

    if (j < 2 && b0 + j < B) {
        float s = b_lin[0];
        #pragma unroll 1
        for (int q = 0; q < HH; q++) s = fmaf(h_sh[j][q], W_lin[q], s);
        out[b0 + j] = s;
    }
}

extern "C" void kernel_launch(void* const* d_in, const int* in_sizes, int n_in,
                              void* d_out, int out_size) {
    const float* x     = (const float*)d_in[0];
    const float* W_ih  = (const float*)d_in[1];
    const float* W_hh  = (const float*)d_in[2];
    const float* b_ih  = (const float*)d_in[3];
    const float* b_hh  = (const float*)d_in[4];
    const float* W_lin = (const float*)d_in[5];
    const float* b_lin = (const float*)d_in[6];
    float* out = (float*)d_out;

    int B = in_sizes[0] / TT;
    int grid = (B + 1) / 2;
    lstm_kernel<<<grid, BT>>>(x, W_ih, W_hh, b_ih, b_hh, W_lin, b_lin, out, B);
}